// round 1
// baseline (speedup 1.0000x reference)
#include <cuda_runtime.h>
#include <math.h>

#define BB 512
#define DD 512
#define LL 24

// Scratch (no allocations allowed in kernel_launch)
__device__ float        g_dist[BB * BB];
__device__ unsigned int g_lab[BB];
__device__ float        g_sum;
__device__ unsigned int g_cnt;

// ---------------------------------------------------------------------------
// Kernel 1: pack labels into 24-bit masks; zero the accumulators.
// sim[i][j] = (lab_i . lab_j > 0)  <=>  (mask_i & mask_j) != 0  (labels are 0/1)
// ---------------------------------------------------------------------------
__global__ void k_pack(const int* __restrict__ labels) {
    int i = blockIdx.x * blockDim.x + threadIdx.x;
    if (i == 0) { g_sum = 0.0f; g_cnt = 0u; }
    if (i < BB) {
        unsigned m = 0u;
#pragma unroll
        for (int l = 0; l < LL; ++l)
            if (labels[i * LL + l] != 0) m |= (1u << l);
        g_lab[i] = m;
    }
}

// ---------------------------------------------------------------------------
// Kernel 2: pairwise euclidean distances. 64x64 output tile per block,
// 256 threads, 4x4 register microtile per thread, K-chunks of 16.
// Tiles stored K-major ([kk][row]) so microtile operands are float4 LDS.
// ---------------------------------------------------------------------------
#define TILE 64
#define KC   16

__global__ __launch_bounds__(256) void k_dist(const float* __restrict__ X) {
    __shared__ float As[KC][TILE + 4];
    __shared__ float Bs[KC][TILE + 4];

    int tid = threadIdx.x;
    int tx = tid & 15;    // 0..15 -> 4 output cols each
    int ty = tid >> 4;    // 0..15 -> 4 output rows each
    int rowBase = blockIdx.y * TILE;
    int colBase = blockIdx.x * TILE;

    float acc[4][4] = {};

    for (int k0 = 0; k0 < DD; k0 += KC) {
        // 64 rows x 16 k-cols per tile; 1024 elems / 256 threads = 4 each.
        for (int t = tid; t < TILE * KC; t += 256) {
            int r = t >> 4;
            int c = t & 15;
            As[c][r] = X[(rowBase + r) * DD + k0 + c];
            Bs[c][r] = X[(colBase + r) * DD + k0 + c];
        }
        __syncthreads();

#pragma unroll
        for (int kk = 0; kk < KC; ++kk) {
            float4 a4 = *reinterpret_cast<const float4*>(&As[kk][ty * 4]);
            float4 b4 = *reinterpret_cast<const float4*>(&Bs[kk][tx * 4]);
            float av[4] = {a4.x, a4.y, a4.z, a4.w};
            float bv[4] = {b4.x, b4.y, b4.z, b4.w};
#pragma unroll
            for (int u = 0; u < 4; ++u)
#pragma unroll
                for (int v = 0; v < 4; ++v) {
                    float d = av[u] - bv[v];
                    acc[u][v] = fmaf(d, d, acc[u][v]);
                }
        }
        __syncthreads();
    }

#pragma unroll
    for (int u = 0; u < 4; ++u)
#pragma unroll
        for (int v = 0; v < 4; ++v) {
            float sq = acc[u][v];
            // reference: dist = (sq == 0) ? 0 : sqrt(sq)
            float dval = (sq > 0.0f) ? sqrtf(sq) : 0.0f;
            g_dist[(rowBase + ty * 4 + u) * BB + (colBase + tx * 4 + v)] = dval;
        }
}

// ---------------------------------------------------------------------------
// Kernel 3: per-anchor triplet accumulation with positive/negative compaction.
// One block per anchor i. Compact d-row into pos/neg lists in SMEM, then sum
// relu(d_ap - d_an) over |P| x |N| pairs (N is tiny for this label dist).
// ---------------------------------------------------------------------------
__global__ __launch_bounds__(256) void k_triplet() {
    int i = blockIdx.x;
    __shared__ float pd[BB];
    __shared__ float nd[BB];
    __shared__ int   np, nn;
    __shared__ float    wsum[8];
    __shared__ unsigned wcnt[8];

    unsigned mi = g_lab[i];
    if (threadIdx.x == 0) { np = 0; nn = 0; }
    __syncthreads();

    const float* drow = &g_dist[i * BB];
    for (int j = threadIdx.x; j < BB; j += blockDim.x) {
        float d = drow[j];
        if (g_lab[j] & mi) pd[atomicAdd(&np, 1)] = d;
        else               nd[atomicAdd(&nn, 1)] = d;
    }
    __syncthreads();

    int P = np, N = nn;
    float    lsum = 0.0f;
    unsigned lcnt = 0u;

    for (int j = threadIdx.x; j < P; j += blockDim.x) {
        float dj = pd[j];
        for (int k = 0; k < N; ++k) {
            float v = dj - nd[k];
            if (v > 1e-16f) { lsum += v; lcnt++; }
        }
    }

    // reduce within block
#pragma unroll
    for (int off = 16; off; off >>= 1) {
        lsum += __shfl_down_sync(0xffffffffu, lsum, off);
        lcnt += __shfl_down_sync(0xffffffffu, lcnt, off);
    }
    int lane = threadIdx.x & 31, wid = threadIdx.x >> 5;
    if (lane == 0) { wsum[wid] = lsum; wcnt[wid] = lcnt; }
    __syncthreads();
    if (wid == 0) {
        lsum = (lane < 8) ? wsum[lane] : 0.0f;
        lcnt = (lane < 8) ? wcnt[lane] : 0u;
#pragma unroll
        for (int off = 4; off; off >>= 1) {
            lsum += __shfl_down_sync(0xffffffffu, lsum, off);
            lcnt += __shfl_down_sync(0xffffffffu, lcnt, off);
        }
        if (lane == 0 && (lcnt != 0u || lsum != 0.0f)) {
            atomicAdd(&g_sum, lsum);
            atomicAdd(&g_cnt, lcnt);
        }
    }
}

// ---------------------------------------------------------------------------
// Kernel 4: finalize  loss = sum / (count + 1e-16)
// ---------------------------------------------------------------------------
__global__ void k_final(float* __restrict__ out) {
    out[0] = (float)((double)g_sum / ((double)g_cnt + 1e-16));
}

extern "C" void kernel_launch(void* const* d_in, const int* in_sizes, int n_in,
                              void* d_out, int out_size) {
    const float* src = (const float*)d_in[0];  // (B, D) float32
    const int*   lab = (const int*)d_in[1];    // (B, L) int32

    k_pack<<<2, 256>>>(lab);
    dim3 grid(BB / TILE, BB / TILE);           // 8 x 8
    k_dist<<<grid, 256>>>(src);
    k_triplet<<<BB, 256>>>();
    k_final<<<1, 1>>>((float*)d_out);
}

// round 2
// speedup vs baseline: 2.1144x; 2.1144x over previous
#include <cuda_runtime.h>
#include <math.h>

#define BB 512
#define DD 512
#define LL 24

#define TM 128
#define TN 64
#define KC 16
#define SPLITS 4
#define KSP (DD / SPLITS)   // 128

// Scratch (device globals — no allocations allowed)
__device__ float        g_part[SPLITS][BB * BB];   // Gram partials per K-split
__device__ float        g_npart[SPLITS][BB];       // diagonal (norm) partials
__device__ unsigned int g_lab[BB];
__device__ float        g_sum;
__device__ unsigned int g_cnt;
__device__ unsigned int g_done;

// ---------------------------------------------------------------------------
// Kernel A: Gram partials G_s = X[:, ks] X[:, ks]^T  (fp32 FMA), 128x64 tile
// per block, 8x4 microtile per thread, K-split over blockIdx.z.
// Block (0,0,0) additionally packs label bitmasks and resets accumulators.
// ---------------------------------------------------------------------------
__global__ __launch_bounds__(256) void k_gram(const float* __restrict__ X,
                                              const int* __restrict__ labels) {
    __shared__ float As[KC][TM + 4];
    __shared__ float Bs[KC][TN + 4];

    int tid = threadIdx.x;

    // side-duty: pack labels + reset accumulators (once, in block 0)
    if (blockIdx.x == 0 && blockIdx.y == 0 && blockIdx.z == 0) {
        for (int i = tid; i < BB; i += 256) {
            unsigned m = 0u;
#pragma unroll
            for (int l = 0; l < LL; ++l)
                if (labels[i * LL + l] != 0) m |= (1u << l);
            g_lab[i] = m;
        }
        if (tid == 0) { g_sum = 0.0f; g_cnt = 0u; g_done = 0u; }
    }

    int tx = tid & 15;          // 16 col-groups of 4
    int ty = tid >> 4;          // 16 row-groups of 8
    int rowBase = blockIdx.y * TM;
    int colBase = blockIdx.x * TN;
    int z       = blockIdx.z;
    int kBase   = z * KSP;

    float acc[8][4] = {};

    for (int k0 = 0; k0 < KSP; k0 += KC) {
        // Load A tile: TM x KC = 128x16 -> 512 float4, 2 per thread
#pragma unroll
        for (int s = 0; s < 2; ++s) {
            int idx = tid + s * 256;           // 0..511
            int r   = idx >> 2;                // 0..127
            int kg  = (idx & 3) * 4;           // 0,4,8,12
            float4 v = *reinterpret_cast<const float4*>(
                &X[(rowBase + r) * DD + kBase + k0 + kg]);
            As[kg + 0][r] = v.x;
            As[kg + 1][r] = v.y;
            As[kg + 2][r] = v.z;
            As[kg + 3][r] = v.w;
        }
        // Load B tile: TN x KC = 64x16 -> 256 float4, 1 per thread
        {
            int r  = tid >> 2;                 // 0..63
            int kg = (tid & 3) * 4;
            float4 v = *reinterpret_cast<const float4*>(
                &X[(colBase + r) * DD + kBase + k0 + kg]);
            Bs[kg + 0][r] = v.x;
            Bs[kg + 1][r] = v.y;
            Bs[kg + 2][r] = v.z;
            Bs[kg + 3][r] = v.w;
        }
        __syncthreads();

#pragma unroll
        for (int kk = 0; kk < KC; ++kk) {
            float4 a0 = *reinterpret_cast<const float4*>(&As[kk][ty * 8]);
            float4 a1 = *reinterpret_cast<const float4*>(&As[kk][ty * 8 + 4]);
            float4 b4 = *reinterpret_cast<const float4*>(&Bs[kk][tx * 4]);
            float av[8] = {a0.x, a0.y, a0.z, a0.w, a1.x, a1.y, a1.z, a1.w};
            float bv[4] = {b4.x, b4.y, b4.z, b4.w};
#pragma unroll
            for (int u = 0; u < 8; ++u)
#pragma unroll
                for (int v = 0; v < 4; ++v)
                    acc[u][v] = fmaf(av[u], bv[v], acc[u][v]);
        }
        __syncthreads();
    }

    // Store tile (vectorized) + diagonal partials
#pragma unroll
    for (int u = 0; u < 8; ++u) {
        int gi = rowBase + ty * 8 + u;
        int gj = colBase + tx * 4;
        float4 v = make_float4(acc[u][0], acc[u][1], acc[u][2], acc[u][3]);
        *reinterpret_cast<float4*>(&g_part[z][gi * BB + gj]) = v;
        int dj = gi - gj;                       // diagonal if 0 <= dj < 4
        if ((unsigned)dj < 4u) g_npart[z][gi] = acc[u][dj];
    }
}

// ---------------------------------------------------------------------------
// Kernel B: per-anchor triplet accumulation (from Gram partials) + finalize.
// dist_ij = sqrt(max(n_i + n_j - 2*G_ij, 0));  diagonal exactly 0 by
// identical summation order of n_i and G_ii.
// Last block to finish writes loss = sum / (count + 1e-16).
// ---------------------------------------------------------------------------
__global__ __launch_bounds__(256) void k_triplet(float* __restrict__ out) {
    int i = blockIdx.x;
    __shared__ float pd[BB];
    __shared__ float nd[BB];
    __shared__ int   np, nn;
    __shared__ float    wsum[8];
    __shared__ unsigned wcnt[8];

    unsigned mi = g_lab[i];
    if (threadIdx.x == 0) { np = 0; nn = 0; }

    float ni = ((g_npart[0][i] + g_npart[1][i]) + g_npart[2][i]) + g_npart[3][i];
    __syncthreads();

    for (int j = threadIdx.x; j < BB; j += blockDim.x) {
        float G  = ((g_part[0][i * BB + j] + g_part[1][i * BB + j]) +
                     g_part[2][i * BB + j]) + g_part[3][i * BB + j];
        float nj = ((g_npart[0][j] + g_npart[1][j]) + g_npart[2][j]) + g_npart[3][j];
        float sq = ni + nj - 2.0f * G;
        float d  = (sq > 0.0f) ? sqrtf(sq) : 0.0f;
        if (g_lab[j] & mi) pd[atomicAdd(&np, 1)] = d;
        else               nd[atomicAdd(&nn, 1)] = d;
    }
    __syncthreads();

    int P = np, N = nn;
    float    lsum = 0.0f;
    unsigned lcnt = 0u;

    if (N > 0) {
        for (int j = threadIdx.x; j < P; j += blockDim.x) {
            float dj = pd[j];
            for (int k = 0; k < N; ++k) {
                float v = dj - nd[k];
                if (v > 1e-16f) { lsum += v; lcnt++; }
            }
        }
    }

    // block reduction
#pragma unroll
    for (int off = 16; off; off >>= 1) {
        lsum += __shfl_down_sync(0xffffffffu, lsum, off);
        lcnt += __shfl_down_sync(0xffffffffu, lcnt, off);
    }
    int lane = threadIdx.x & 31, wid = threadIdx.x >> 5;
    if (lane == 0) { wsum[wid] = lsum; wcnt[wid] = lcnt; }
    __syncthreads();
    if (wid == 0) {
        lsum = (lane < 8) ? wsum[lane] : 0.0f;
        lcnt = (lane < 8) ? wcnt[lane] : 0u;
#pragma unroll
        for (int off = 4; off; off >>= 1) {
            lsum += __shfl_down_sync(0xffffffffu, lsum, off);
            lcnt += __shfl_down_sync(0xffffffffu, lcnt, off);
        }
        if (lane == 0) {
            if (lcnt != 0u || lsum != 0.0f) {
                atomicAdd(&g_sum, lsum);
                atomicAdd(&g_cnt, lcnt);
            }
            __threadfence();
            unsigned prev = atomicAdd(&g_done, 1u);
            if (prev == (unsigned)(gridDim.x - 1)) {
                float s = *((volatile float*)&g_sum);
                unsigned c = *((volatile unsigned*)&g_cnt);
                out[0] = (float)((double)s / ((double)c + 1e-16));
            }
        }
    }
}

extern "C" void kernel_launch(void* const* d_in, const int* in_sizes, int n_in,
                              void* d_out, int out_size) {
    const float* src = (const float*)d_in[0];  // (B, D) float32
    const int*   lab = (const int*)d_in[1];    // (B, L) int32

    dim3 grid(BB / TN, BB / TM, SPLITS);       // 8 x 4 x 4 = 128 blocks
    k_gram<<<grid, 256>>>(src, lab);
    k_triplet<<<BB, 256>>>((float*)d_out);
}